// round 16
// baseline (speedup 1.0000x reference)
#include <cuda_runtime.h>
#include <cstdint>

#define BATCH 1024
#define NUM_CLS 58

typedef unsigned long long ull;

// ---------------- device scratch (no allocations allowed) ----------------
__device__ unsigned g_pw1[9 * 4 * 128];   // packed w1 signs, layout [tap][word][oc]
__device__ unsigned g_pw2[9 * 4 * 128];
__device__ unsigned g_pw3[9 * 4 * 128];
__device__ unsigned g_pw4[4 * 128];       // layout [word][oc]

// ---------------- f32x2 helpers (packed dual-fp32, sm_103a FFMA2) ----------------
__device__ __forceinline__ ull pk2(float a, float b) {
    ull r;
    asm("mov.b64 %0, {%1, %2};" : "=l"(r) : "f"(a), "f"(b));
    return r;
}
__device__ __forceinline__ void fma2(ull& d, ull a, ull b) {
    asm("fma.rn.f32x2 %0, %1, %2, %0;" : "+l"(d) : "l"(a), "l"(b));
}
__device__ __forceinline__ float2 upk(ull v) {
    float2 f;
    asm("mov.b64 {%0, %1}, %2;" : "=f"(f.x), "=f"(f.y) : "l"(v));
    return f;
}
__device__ __forceinline__ int popc4(uint4 a, uint4 b) {
    return __popc(a.x ^ b.x) + __popc(a.y ^ b.y) + __popc(a.z ^ b.z) + __popc(a.w ^ b.w);
}

// ---------------- weight sign packing (warp-ballot, coalesced) ----------------
__global__ void pack_weights_kernel(const float* __restrict__ w1, const float* __restrict__ w2,
                                    const float* __restrict__ w3, const float* __restrict__ w4) {
    int gw   = (blockIdx.x * blockDim.x + threadIdx.x) >> 5;
    int lane = threadIdx.x & 31;
    if (gw >= 2048) return;
    int t  = gw >> 9;
    int r  = gw & 511;
    int oc = r >> 2;
    int wi = r & 3;
    if (t < 3) {
        const float* w = (t == 0) ? w1 : ((t == 1) ? w2 : w3);
        unsigned* pw   = (t == 0) ? g_pw1 : ((t == 1) ? g_pw2 : g_pw3);
        const float* p = w + ((size_t)(oc * 128 + wi * 32 + lane)) * 9;
        float v[9];
#pragma unroll
        for (int k = 0; k < 9; k++) v[k] = p[k];
        unsigned myword = 0;
#pragma unroll
        for (int tap = 0; tap < 9; tap++) {
            unsigned wd = __ballot_sync(0xffffffffu, v[tap] >= 0.0f);
            if (lane == tap) myword = wd;
        }
        if (lane < 9) pw[(lane * 4 + wi) * 128 + oc] = myword;
    } else {
        float v = w4[oc * 128 + wi * 32 + lane];
        unsigned wd = __ballot_sync(0xffffffffu, v >= 0.0f);
        if (lane == 0) g_pw4[wi * 128 + oc] = wd;
    }
}

// ---- phase-0 helper: PIX pooled pixels; f32x2 pairs via WIDE smem loads ----
// (bit-identical accumulation order: c asc, ky asc, kx asc)
template<int PIX>
__device__ __forceinline__ void conv_group(const float* __restrict__ xs,
                                           const float* __restrict__ xsh,
                                           int y0, int x0c,
                                           const float* __restrict__ wr,
                                           int cg, unsigned* __restrict__ a1w,
                                           int pbase, int lane) {
    constexpr int NP = 2 * PIX + 1;
    ull A0[PIX], A1[PIX];
#pragma unroll
    for (int pi = 0; pi < PIX; pi++) { A0[pi] = 0ull; A1[pi] = 0ull; }

#pragma unroll
    for (int c = 0; c < 3; c++) {
        ull wp[9];
#pragma unroll
        for (int k = 0; k < 9; k++) { float w = wr[c * 9 + k]; wp[k] = pk2(w, w); }
#pragma unroll
        for (int dy = 0; dy < 4; dy++) {
            int idx = c * 1024 + (y0 + dy) * 32 + x0c;
            ull pr[NP];
            {
                ulonglong2 q0 = *(const ulonglong2*)&xs[idx];
                ulonglong2 q1 = *(const ulonglong2*)&xs[idx + 4];
                ulonglong2 s0 = *(const ulonglong2*)&xsh[idx];
                pr[0] = q0.x; pr[2] = q0.y;
                pr[4] = q1.x; pr[6] = q1.y;
                pr[1] = s0.x; pr[3] = s0.y;
                if (PIX == 4) {
                    ulonglong2 s1 = *(const ulonglong2*)&xsh[idx + 4];
                    pr[5] = s1.x; pr[7] = s1.y;
                    pr[8] = *(const ull*)&xs[idx + 8];
                } else {
                    pr[5] = *(const ull*)&xsh[idx + 4];
                }
            }
#pragma unroll
            for (int kx = 0; kx < 3; kx++) {
                if (dy <= 2) {
                    ull w = wp[dy * 3 + kx];
#pragma unroll
                    for (int pi = 0; pi < PIX; pi++) fma2(A0[pi], pr[2 * pi + kx], w);
                }
                if (dy >= 1) {
                    ull w = wp[(dy - 1) * 3 + kx];
#pragma unroll
                    for (int pi = 0; pi < PIX; pi++) fma2(A1[pi], pr[2 * pi + kx], w);
                }
            }
        }
    }
#pragma unroll
    for (int pi = 0; pi < PIX; pi++) {
        float2 v0 = upk(A0[pi]);
        float2 v1 = upk(A1[pi]);
        float best = fmaxf(fmaxf(v0.x, v0.y), fmaxf(v1.x, v1.y));
        unsigned word = __ballot_sync(0xffffffffu, best >= 0.0f);
        if (lane == 0) a1w[(pbase + pi) * 4 + cg] = word;
    }
}

__device__ __forceinline__ void conv_row(const float* xs, const float* xsh, int py,
                                         const float* wr, int cg, unsigned* a1w, int lane) {
    int y0 = 2 * py, pb = py * 15;
    conv_group<4>(xs, xsh, y0, 0,  wr, cg, a1w, pb + 0,  lane);
    conv_group<4>(xs, xsh, y0, 8,  wr, cg, a1w, pb + 4,  lane);
    conv_group<4>(xs, xsh, y0, 16, wr, cg, a1w, pb + 8,  lane);
    conv_group<3>(xs, xsh, y0, 24, wr, cg, a1w, pb + 12, lane);
}

// ---- binconv pixel (streaming rows; integer sums are order-exact) ----
template<int W>   // input width in uint4 pixels (15 for a1, 6 for a2)
__device__ __forceinline__ void binconv_px(int p, int ow, const uint4* __restrict__ av,
                                           const uint4* __restrict__ wr,
                                           unsigned* __restrict__ dst, int cg, int lane) {
    int py = p / ow, px = p - py * ow;
    int y0 = (W == 15) ? 2 * py : py;      // binconv1 pools stride 2, binconv2 stride 1
    int x0 = (W == 15) ? 2 * px : px;

    int s00 = 0, s01 = 0, s10 = 0, s11 = 0;
#pragma unroll
    for (int dy = 0; dy < 4; dy++) {
        const uint4* row = &av[(y0 + dy) * W + x0];
        uint4 r0 = row[0], r1 = row[1], r2 = row[2], r3 = row[3];
        if (dy <= 2) {
            uint4 wa = wr[dy * 3 + 0], wb = wr[dy * 3 + 1], wc = wr[dy * 3 + 2];
            s00 += popc4(r0, wa) + popc4(r1, wb) + popc4(r2, wc);
            s01 += popc4(r1, wa) + popc4(r2, wb) + popc4(r3, wc);
        }
        if (dy >= 1) {
            uint4 wa = wr[(dy - 1) * 3 + 0], wb = wr[(dy - 1) * 3 + 1], wc = wr[(dy - 1) * 3 + 2];
            s10 += popc4(r0, wa) + popc4(r1, wb) + popc4(r2, wc);
            s11 += popc4(r1, wa) + popc4(r2, wb) + popc4(r3, wc);
        }
    }
    int smin = min(min(s00, s01), min(s10, s11));
    unsigned word = __ballot_sync(0xffffffffu, smin <= 576);
    if (lane == 0) dst[p * 4 + cg] = word;
}

// ---------------- merged model kernel: block = TWO images (A,B), 128 threads ----------------
// Phase-shifted software pipeline: B.conv (FMA) interleaves with A.binconv1 (ALU)
// in one instruction stream — pipe mixing + dual-stream ILP. grid = 512.
__global__ __launch_bounds__(128, 4) void model_kernel(const float* __restrict__ x,
                                                       const float* __restrict__ w0,
                                                       const float* __restrict__ w5,
                                                       float* __restrict__ out) {
    __shared__ __align__(16) float xsA[3072];
    __shared__ __align__(16) float xsB[3072];
    __shared__ __align__(16) float xsh[3072];     // shifted shadow: A then B
    __shared__ uint4 a1A[225], a1B[225];
    __shared__ uint4 a2A[36], a2B[36];
    __shared__ uint4 a3A[9], a3B[9];
    __shared__ unsigned s4A[4], s4B[4];
    __shared__ float rsA[128], rsB[128];
    __shared__ float lgA[NUM_CLS], lgB[NUM_CLS];

    int bA   = 2 * blockIdx.x;
    int bB   = bA + 1;
    int tid  = threadIdx.x;
    int warp = tid >> 5;
    int lane = tid & 31;
    int cg   = warp;
    int oc   = cg * 32 + lane;

    // ---- load both images ----
    {
        const float4* a4 = (const float4*)(x + (size_t)bA * 3072);
        const float4* b4 = (const float4*)(x + (size_t)bB * 3072);
        float4* sA = (float4*)xsA;
        float4* sB = (float4*)xsB;
        for (int i = tid; i < 768; i += 128) { sA[i] = a4[i]; sB[i] = b4[i]; }
    }
    __syncthreads();
    for (int i = tid; i < 3071; i += 128) xsh[i] = xsA[i + 1];
    __syncthreads();

    // conv weights (register-resident for stages 2-3)
    float wr0[27];
#pragma unroll
    for (int k = 0; k < 27; k++) wr0[k] = w0[oc * 27 + k];

    // ---- stage 2: A.conv (pure FMA window) ----
    for (int py = 0; py < 15; py++)
        conv_row(xsA, xsh, py, wr0, cg, (unsigned*)a1A, lane);
    __syncthreads();
    for (int i = tid; i < 3071; i += 128) xsh[i] = xsB[i + 1];   // re-point shadow to B
    __syncthreads();

    // binconv1 weights (register-resident, shared by A and B)
    uint4 wr1[9];
#pragma unroll
    for (int tap = 0; tap < 9; tap++) {
        wr1[tap].x = g_pw1[(tap * 4 + 0) * 128 + oc];
        wr1[tap].y = g_pw1[(tap * 4 + 1) * 128 + oc];
        wr1[tap].z = g_pw1[(tap * 4 + 2) * 128 + oc];
        wr1[tap].w = g_pw1[(tap * 4 + 3) * 128 + oc];
    }

    // ---- stage 3 (MIXED): B.conv row py (FMA)  +  A.binconv1 pixels (ALU) ----
    for (int py = 0; py < 15; py++) {
        conv_row(xsB, xsh, py, wr0, cg, (unsigned*)a1B, lane);
        int p0 = (py * 12) / 5, p1 = ((py + 1) * 12) / 5;     // 36 pixels over 15 iters
        for (int p = p0; p < p1; p++)
            binconv_px<15>(p, 6, a1A, wr1, (unsigned*)a2A, cg, lane);
    }
    __syncthreads();

    // binconv2 weights
    uint4 wr2[9];
#pragma unroll
    for (int tap = 0; tap < 9; tap++) {
        wr2[tap].x = g_pw2[(tap * 4 + 0) * 128 + oc];
        wr2[tap].y = g_pw2[(tap * 4 + 1) * 128 + oc];
        wr2[tap].z = g_pw2[(tap * 4 + 2) * 128 + oc];
        wr2[tap].w = g_pw2[(tap * 4 + 3) * 128 + oc];
    }

    // ---- stage 4 (interleaved ILP): B.binconv1 (36 px) + A.binconv2 (9 px) ----
    for (int i = 0; i < 9; i++) {
#pragma unroll
        for (int j = 0; j < 4; j++)
            binconv_px<15>(4 * i + j, 6, a1B, wr1, (unsigned*)a2B, cg, lane);
        binconv_px<6>(i, 3, a2A, wr2, (unsigned*)a3A, cg, lane);
    }
    __syncthreads();

    // ---- stage 5: B.binconv2 (9 px) ----
    for (int p = 0; p < 9; p++)
        binconv_px<6>(p, 3, a2B, wr2, (unsigned*)a3B, cg, lane);
    __syncthreads();

    // ---- heads A and B fused ----
    {
        int sA = 0, sB = 0;
#pragma unroll
        for (int tap = 0; tap < 9; tap++) {
            uint4 xa = a3A[tap], xb = a3B[tap];
            unsigned w0t = g_pw3[(tap * 4 + 0) * 128 + tid];
            unsigned w1t = g_pw3[(tap * 4 + 1) * 128 + tid];
            unsigned w2t = g_pw3[(tap * 4 + 2) * 128 + tid];
            unsigned w3t = g_pw3[(tap * 4 + 3) * 128 + tid];
            sA += __popc(xa.x ^ w0t) + __popc(xa.y ^ w1t) + __popc(xa.z ^ w2t) + __popc(xa.w ^ w3t);
            sB += __popc(xb.x ^ w0t) + __popc(xb.y ^ w1t) + __popc(xb.z ^ w2t) + __popc(xb.w ^ w3t);
        }
        unsigned wa = __ballot_sync(0xffffffffu, sA <= 576);
        unsigned wb = __ballot_sync(0xffffffffu, sB <= 576);
        if (lane == 0) { s4A[warp] = wa; s4B[warp] = wb; }
    }
    __syncthreads();

    {
        int tA = 0, tB = 0;
#pragma unroll
        for (int wi = 0; wi < 4; wi++) {
            unsigned w4t = g_pw4[wi * 128 + tid];
            tA += __popc(s4A[wi] ^ w4t);
            tB += __popc(s4B[wi] ^ w4t);
        }
        rsA[tid] = fmaxf((float)(128 - 2 * tA), 0.0f);
        rsB[tid] = fmaxf((float)(128 - 2 * tB), 0.0f);
    }
    __syncthreads();

    if (tid < NUM_CLS) {
        float accA = 0.0f, accB = 0.0f;
#pragma unroll 8
        for (int o = 0; o < 128; o++) {
            float w = w5[tid * 128 + o];
            accA += w * rsA[o];
            accB += w * rsB[o];
        }
        lgA[tid] = accA;
        lgB[tid] = accB;
    }
    __syncthreads();

    if (tid < NUM_CLS) {
        float mA = -3.4e38f, mB = -3.4e38f;
        for (int j = 0; j < NUM_CLS; j++) { mA = fmaxf(mA, lgA[j]); mB = fmaxf(mB, lgB[j]); }
        float dA = 0.0f, dB = 0.0f;
        for (int j = 0; j < NUM_CLS; j++) { dA += expf(lgA[j] - mA); dB += expf(lgB[j] - mB); }
        out[(size_t)bA * NUM_CLS + tid] = expf(lgA[tid] - mA) / dA;
        out[(size_t)bB * NUM_CLS + tid] = expf(lgB[tid] - mB) / dB;
    }
}

// ---------------- launch ----------------
extern "C" void kernel_launch(void* const* d_in, const int* in_sizes, int n_in,
                              void* d_out, int out_size) {
    const float* x  = (const float*)d_in[0];
    const float* w0 = (const float*)d_in[1];
    const float* w1 = (const float*)d_in[2];
    const float* w2 = (const float*)d_in[3];
    const float* w3 = (const float*)d_in[4];
    const float* w4 = (const float*)d_in[5];
    const float* w5 = (const float*)d_in[6];
    float* out = (float*)d_out;

    pack_weights_kernel<<<256, 256>>>(w1, w2, w3, w4);
    model_kernel<<<BATCH / 2, 128>>>(x, w0, w5, out);
}

// round 17
// speedup vs baseline: 1.0653x; 1.0653x over previous
#include <cuda_runtime.h>
#include <cstdint>

#define BATCH 1024
#define NUM_CLS 58

typedef unsigned long long ull;

// ---------------- device scratch (no allocations allowed) ----------------
__device__ unsigned g_pw1[9 * 4 * 128];   // packed w1 signs, layout [tap][word][oc]
__device__ unsigned g_pw2[9 * 4 * 128];
__device__ unsigned g_pw3[9 * 4 * 128];
__device__ unsigned g_pw4[4 * 128];       // layout [word][oc]

// ---------------- f32x2 helpers (packed dual-fp32, sm_103a FFMA2) ----------------
__device__ __forceinline__ ull pk2(float a, float b) {
    ull r;
    asm("mov.b64 %0, {%1, %2};" : "=l"(r) : "f"(a), "f"(b));
    return r;
}
__device__ __forceinline__ void fma2(ull& d, ull a, ull b) {
    asm("fma.rn.f32x2 %0, %1, %2, %0;" : "+l"(d) : "l"(a), "l"(b));
}
__device__ __forceinline__ float2 upk(ull v) {
    float2 f;
    asm("mov.b64 {%0, %1}, %2;" : "=f"(f.x), "=f"(f.y) : "l"(v));
    return f;
}
__device__ __forceinline__ int popc4(uint4 a, uint4 b) {
    return __popc(a.x ^ b.x) + __popc(a.y ^ b.y) + __popc(a.z ^ b.z) + __popc(a.w ^ b.w);
}

// ---------------- weight sign packing (warp-ballot, coalesced) ----------------
__global__ void pack_weights_kernel(const float* __restrict__ w1, const float* __restrict__ w2,
                                    const float* __restrict__ w3, const float* __restrict__ w4) {
    int gw   = (blockIdx.x * blockDim.x + threadIdx.x) >> 5;
    int lane = threadIdx.x & 31;
    if (gw >= 2048) return;
    int t  = gw >> 9;
    int r  = gw & 511;
    int oc = r >> 2;
    int wi = r & 3;
    if (t < 3) {
        const float* w = (t == 0) ? w1 : ((t == 1) ? w2 : w3);
        unsigned* pw   = (t == 0) ? g_pw1 : ((t == 1) ? g_pw2 : g_pw3);
        const float* p = w + ((size_t)(oc * 128 + wi * 32 + lane)) * 9;
        float v[9];
#pragma unroll
        for (int k = 0; k < 9; k++) v[k] = p[k];
        unsigned myword = 0;
#pragma unroll
        for (int tap = 0; tap < 9; tap++) {
            unsigned wd = __ballot_sync(0xffffffffu, v[tap] >= 0.0f);
            if (lane == tap) myword = wd;
        }
        if (lane < 9) pw[(lane * 4 + wi) * 128 + oc] = myword;
    } else {
        float v = w4[oc * 128 + wi * 32 + lane];
        unsigned wd = __ballot_sync(0xffffffffu, v >= 0.0f);
        if (lane == 0) g_pw4[wi * 128 + oc] = wd;
    }
}

// ---- phase-0 helper: PIX pooled pixels sharing 12-col row loads, FFMA2 packed ----
// (R11 verbatim — measured best. Per-candidate accumulation order (c,ky,kx) asc.)
template<int PIX>
__device__ __forceinline__ void conv_group(const float* __restrict__ xs, int y0, int x0c,
                                           const float* __restrict__ wr, int cg,
                                           unsigned* __restrict__ a1w, int pbase, int lane) {
    constexpr int NW = (PIX == 4) ? 3 : 2;    // float4 loads per row
    constexpr int NP = 2 * PIX + 1;           // adjacent pairs (e[s],e[s+1])
    ull A0[PIX], A1[PIX];                     // cy=0 / cy=1, each = (cx0,cx1)
#pragma unroll
    for (int pi = 0; pi < PIX; pi++) { A0[pi] = 0ull; A1[pi] = 0ull; }

#pragma unroll
    for (int c = 0; c < 3; c++) {
        ull wp[9];
#pragma unroll
        for (int k = 0; k < 9; k++) { float w = wr[c * 9 + k]; wp[k] = pk2(w, w); }
#pragma unroll
        for (int dy = 0; dy < 4; dy++) {
            float e[NW * 4];
            const float4* r4 = (const float4*)&xs[c * 1024 + (y0 + dy) * 32 + x0c];
#pragma unroll
            for (int j = 0; j < NW; j++) {
                float4 q = r4[j];
                e[j * 4 + 0] = q.x; e[j * 4 + 1] = q.y; e[j * 4 + 2] = q.z; e[j * 4 + 3] = q.w;
            }
            ull pr[NP];
#pragma unroll
            for (int s = 0; s < NP; s++) pr[s] = pk2(e[s], e[s + 1]);
#pragma unroll
            for (int kx = 0; kx < 3; kx++) {
                if (dy <= 2) {
                    ull w = wp[dy * 3 + kx];
#pragma unroll
                    for (int pi = 0; pi < PIX; pi++) fma2(A0[pi], pr[2 * pi + kx], w);
                }
                if (dy >= 1) {
                    ull w = wp[(dy - 1) * 3 + kx];
#pragma unroll
                    for (int pi = 0; pi < PIX; pi++) fma2(A1[pi], pr[2 * pi + kx], w);
                }
            }
        }
    }
#pragma unroll
    for (int pi = 0; pi < PIX; pi++) {
        float2 v0 = upk(A0[pi]);
        float2 v1 = upk(A1[pi]);
        float best = fmaxf(fmaxf(v0.x, v0.y), fmaxf(v1.x, v1.y));
        unsigned word = __ballot_sync(0xffffffffu, best >= 0.0f);
        if (lane == 0) a1w[(pbase + pi) * 4 + cg] = word;
    }
}

// ---------------- single merged model kernel: block = image, 128 threads (4 warps) ----------------
__global__ __launch_bounds__(128, 7) void model_kernel(const float* __restrict__ x,
                                                       const float* __restrict__ w0,
                                                       const float* __restrict__ w5,
                                                       float* __restrict__ out) {
    __shared__ float xs[3 * 32 * 32];
    __shared__ uint4 a1s[225];
    __shared__ uint4 a2v[36];
    __shared__ uint4 a3v[9];
    __shared__ unsigned s4w[4];
    __shared__ float rs[128];
    __shared__ float lg[NUM_CLS];

    int b    = blockIdx.x;
    int tid  = threadIdx.x;
    int warp = tid >> 5;
    int lane = tid & 31;

    // ---- load image ----
    const float4* xb4 = (const float4*)(x + (size_t)b * 3072);
    float4* xs4 = (float4*)xs;
    for (int i = tid; i < 768; i += 128) xs4[i] = xb4[i];
    __syncthreads();

    // ---- phase 0: conv0 + pool + sign + pack (4 warps: cg = warp) ----
    {
        int cg = warp;
        int oc = cg * 32 + lane;

        float wr[27];
#pragma unroll
        for (int k = 0; k < 27; k++) wr[k] = w0[oc * 27 + k];

        unsigned* a1w = (unsigned*)a1s;
        for (int py = 0; py < 15; py++) {
            int y0 = 2 * py;
            int pb = py * 15;
            conv_group<4>(xs, y0, 0,  wr, cg, a1w, pb + 0,  lane);
            conv_group<4>(xs, y0, 8,  wr, cg, a1w, pb + 4,  lane);
            conv_group<4>(xs, y0, 16, wr, cg, a1w, pb + 8,  lane);
            conv_group<3>(xs, y0, 24, wr, cg, a1w, pb + 12, lane);
        }
    }
    __syncthreads();

    // ---- phase 1: binconv1, DUAL-PIXEL streaming rows ----
    // Adjacent pixels (px, px+1) share a 6-wide row window: one load feeds 8
    // independent popc chains (2 pixels x 4 pool candidates). Integer order-exact.
    {
        int cg = warp;
        int oc = cg * 32 + lane;

        uint4 wr[9];
#pragma unroll
        for (int tap = 0; tap < 9; tap++) {
            wr[tap].x = g_pw1[(tap * 4 + 0) * 128 + oc];
            wr[tap].y = g_pw1[(tap * 4 + 1) * 128 + oc];
            wr[tap].z = g_pw1[(tap * 4 + 2) * 128 + oc];
            wr[tap].w = g_pw1[(tap * 4 + 3) * 128 + oc];
        }

        for (int py = 0; py < 6; py++) {
            int y0 = 2 * py;
#pragma unroll
            for (int pxp = 0; pxp < 6; pxp += 2) {
                int x0 = 2 * pxp;        // pixel0 cols x0..x0+3, pixel1 cols x0+2..x0+5 (<=13)
                int s00 = 0, s01 = 0, s10 = 0, s11 = 0;   // pixel pxp
                int t00 = 0, t01 = 0, t10 = 0, t11 = 0;   // pixel pxp+1
#pragma unroll
                for (int dy = 0; dy < 4; dy++) {
                    const uint4* row = &a1s[(y0 + dy) * 15 + x0];
                    uint4 r0 = row[0], r1 = row[1], r2 = row[2],
                          r3 = row[3], r4 = row[4], r5 = row[5];
                    if (dy <= 2) {
                        uint4 wa = wr[dy * 3 + 0], wb = wr[dy * 3 + 1], wc = wr[dy * 3 + 2];
                        s00 += popc4(r0, wa) + popc4(r1, wb) + popc4(r2, wc);
                        s01 += popc4(r1, wa) + popc4(r2, wb) + popc4(r3, wc);
                        t00 += popc4(r2, wa) + popc4(r3, wb) + popc4(r4, wc);
                        t01 += popc4(r3, wa) + popc4(r4, wb) + popc4(r5, wc);
                    }
                    if (dy >= 1) {
                        uint4 wa = wr[(dy - 1) * 3 + 0], wb = wr[(dy - 1) * 3 + 1], wc = wr[(dy - 1) * 3 + 2];
                        s10 += popc4(r0, wa) + popc4(r1, wb) + popc4(r2, wc);
                        s11 += popc4(r1, wa) + popc4(r2, wb) + popc4(r3, wc);
                        t10 += popc4(r2, wa) + popc4(r3, wb) + popc4(r4, wc);
                        t11 += popc4(r3, wa) + popc4(r4, wb) + popc4(r5, wc);
                    }
                }
                int smin0 = min(min(s00, s01), min(s10, s11));
                int smin1 = min(min(t00, t01), min(t10, t11));
                // dot = 1152 - 2*smin ; sign bit = (dot >= 0)
                unsigned word0 = __ballot_sync(0xffffffffu, smin0 <= 576);
                unsigned word1 = __ballot_sync(0xffffffffu, smin1 <= 576);
                if (lane == 0) {
                    int p = py * 6 + pxp;
                    ((unsigned*)a2v)[p * 4 + cg]       = word0;
                    ((unsigned*)a2v)[(p + 1) * 4 + cg] = word1;
                }
            }
        }
    }
    __syncthreads();

    // ---- phase 2: binconv2 (4 warps: cg = warp, 9 pixels each) ----
    {
        int cg = warp;
        int oc = cg * 32 + lane;

        uint4 wr[9];
#pragma unroll
        for (int tap = 0; tap < 9; tap++) {
            wr[tap].x = g_pw2[(tap * 4 + 0) * 128 + oc];
            wr[tap].y = g_pw2[(tap * 4 + 1) * 128 + oc];
            wr[tap].z = g_pw2[(tap * 4 + 2) * 128 + oc];
            wr[tap].w = g_pw2[(tap * 4 + 3) * 128 + oc];
        }

        for (int p = 0; p < 9; p++) {
            int py = p / 3, px = p - py * 3;

            int smin = 1 << 30;
#pragma unroll
            for (int cy = 0; cy < 2; cy++)
#pragma unroll
                for (int cx = 0; cx < 2; cx++) {
                    int s = 0;
#pragma unroll
                    for (int ky = 0; ky < 3; ky++)
#pragma unroll
                        for (int kx = 0; kx < 3; kx++) {
                            uint4 xv = a2v[(py + cy + ky) * 6 + (px + cx + kx)];
                            uint4 wv = wr[ky * 3 + kx];
                            s += popc4(xv, wv);
                        }
                    smin = min(smin, s);
                }
            unsigned word = __ballot_sync(0xffffffffu, smin <= 576);
            if (lane == 0) ((unsigned*)a3v)[p * 4 + cg] = word;
        }
    }
    __syncthreads();

    // ---- phase 3: head (128 threads = output channel) ----
    {
        int s = 0;
#pragma unroll
        for (int tap = 0; tap < 9; tap++) {
            uint4 xv = a3v[tap];
            s += __popc(xv.x ^ g_pw3[(tap * 4 + 0) * 128 + tid]);
            s += __popc(xv.y ^ g_pw3[(tap * 4 + 1) * 128 + tid]);
            s += __popc(xv.z ^ g_pw3[(tap * 4 + 2) * 128 + tid]);
            s += __popc(xv.w ^ g_pw3[(tap * 4 + 3) * 128 + tid]);
        }
        unsigned word = __ballot_sync(0xffffffffu, s <= 576);  // sign(1152 - 2s)
        if (lane == 0) s4w[warp] = word;
    }
    __syncthreads();

    {
        int t = 0;
#pragma unroll
        for (int wi = 0; wi < 4; wi++) t += __popc(s4w[wi] ^ g_pw4[wi * 128 + tid]);
        rs[tid] = fmaxf((float)(128 - 2 * t), 0.0f);
    }
    __syncthreads();

    // fp32 1x1 conv to NUM_CLS logits
    if (tid < NUM_CLS) {
        float acc = 0.0f;
#pragma unroll 8
        for (int o = 0; o < 128; o++) acc += w5[tid * 128 + o] * rs[o];
        lg[tid] = acc;
    }
    __syncthreads();

    // softmax over NUM_CLS
    if (tid < NUM_CLS) {
        float m = -3.4e38f;
        for (int j = 0; j < NUM_CLS; j++) m = fmaxf(m, lg[j]);
        float den = 0.0f;
        for (int j = 0; j < NUM_CLS; j++) den += expf(lg[j] - m);
        out[(size_t)b * NUM_CLS + tid] = expf(lg[tid] - m) / den;
    }
}

// ---------------- launch ----------------
extern "C" void kernel_launch(void* const* d_in, const int* in_sizes, int n_in,
                              void* d_out, int out_size) {
    const float* x  = (const float*)d_in[0];
    const float* w0 = (const float*)d_in[1];
    const float* w1 = (const float*)d_in[2];
    const float* w2 = (const float*)d_in[3];
    const float* w3 = (const float*)d_in[4];
    const float* w4 = (const float*)d_in[5];
    const float* w5 = (const float*)d_in[6];
    float* out = (float*)d_out;

    pack_weights_kernel<<<256, 256>>>(w1, w2, w3, w4);
    model_kernel<<<BATCH, 128>>>(x, w0, w5, out);
}